// round 6
// baseline (speedup 1.0000x reference)
#include <cuda_runtime.h>

// MultiChannelSpikingAttention — GB300, fused single kernel, CHUNK=128.
//
//   v_t = d*v_{t-1} + x_t ; s = (v>=1); v -= s     (3 ch, 512 rows, 8192 steps)
//   sal[b,t] = sum_c w[c]*s ;  sal /= (rowmax + 1e-6)
//   top5 (stable), mu = 0.5 + 2*tanh(1.8*mean(top5))
//   out = concat(mu[512], sal[512*8192], topk_idx[512*5] as f32)
//
// One block per row; 64 scan threads (chunks of 128) + 320-step warm-up that
// resynchronizes the reset map. Non-fused mul/add matches XLA bit-exactly.
// Smem: 132-float region per chunk -> lane stride 33*16B (odd) => conflict-free
// LDS/STS.128. Raw sal overwrites the channel-0 region in place.

#define B_DIM 512
#define T_DIM 8192
#define NTH   128                  // block threads
#define NSC   64                   // scan threads = chunks per row
#define CHUNK 128
#define WARM  320
#define REG   132                  // floats per chunk region (128 + 4 pad)
#define CH_STRIDE (NSC * REG)      // 8448 floats per channel
#define SMEM_BYTES (3 * CH_STRIDE * 4 + NSC * 8 + NSC * 4)   // 102144 B

// padded smem float-offset for global float4 index g
__device__ __forceinline__ int offq(int g) {
    return (g >> 5) * REG + ((g & 31) << 2);
}

// warm-up step: state only (XLA-matching rounding, no fma)
__device__ __forceinline__ void stepw(float& v, float d, float x) {
    float a = __fadd_rn(__fmul_rn(d, v), x);
    v = (a >= 1.0f) ? __fadd_rn(a, -1.0f) : a;
}
// main step: returns w on spike else 0
__device__ __forceinline__ float stepm(float& v, float d, float x, float w) {
    float a = __fadd_rn(__fmul_rn(d, v), x);
    bool  s = (a >= 1.0f);
    v = s ? __fadd_rn(a, -1.0f) : a;
    return s ? w : 0.0f;
}

// packed key: (float bits << 32) | ~index -> max = max value, ties -> smaller
// index (matches jax.lax.top_k stability); values >= 0 so bits are monotone.
__device__ __forceinline__ void ins5(unsigned long long* loc, float v, int t) {
    unsigned long long key =
        ((unsigned long long)__float_as_uint(v) << 32) | (unsigned)(~t);
    if (key > loc[4]) {
        loc[4] = key;
#pragma unroll
        for (int k = 4; k > 0; k--) {
            if (loc[k] > loc[k-1]) {
                unsigned long long tmp = loc[k]; loc[k] = loc[k-1]; loc[k-1] = tmp;
            }
        }
    }
}

__global__ void __launch_bounds__(NTH) fused_kernel(
    const float* __restrict__ amp, const float* __restrict__ pitch,
    const float* __restrict__ boundary, const float* __restrict__ decay,
    const float* __restrict__ weights,
    float* __restrict__ mu, float* __restrict__ salg, float* __restrict__ idx_out)
{
    extern __shared__ float sm[];
    float* s0 = sm;
    float* s1 = sm + CH_STRIDE;
    float* s2 = sm + 2 * CH_STRIDE;
    unsigned long long* redu = (unsigned long long*)(sm + 3 * CH_STRIDE);
    float*              redf = (float*)(redu + NSC);

    int b = blockIdx.x;
    int t = threadIdx.x;

    // ---- stage 3 channels, coalesced LDG.128 -> padded smem ----
    {
        const float4* srcA = (const float4*)(amp      + (size_t)b * T_DIM);
        const float4* srcP = (const float4*)(pitch    + (size_t)b * T_DIM);
        const float4* srcQ = (const float4*)(boundary + (size_t)b * T_DIM);
#pragma unroll
        for (int r = 0; r < T_DIM / 4 / NTH; r++) {
            int g = t + r * NTH;
            int a = offq(g);
            *(float4*)(s0 + a) = srcA[g];
            *(float4*)(s1 + a) = srcP[g];
            *(float4*)(s2 + a) = srcQ[g];
        }
    }

    float d0 = decay[0],   d1 = decay[1],   d2 = decay[2];
    float w0 = weights[0], w1 = weights[1], w2 = weights[2];
    __syncthreads();

    float v0 = 0.f, v1 = 0.f, v2 = 0.f;
    int start = t * CHUNK;

    // ---- warm-up (scan threads only, no emit) ----
    if (t < NSC) {
        int gs = (start >= WARM) ? ((start - WARM) >> 2) : 0;
        int ge = start >> 2;
        if (gs < ge) {
            int a0 = offq(gs);
            float4 xa = *(const float4*)(s0 + a0);
            float4 xp = *(const float4*)(s1 + a0);
            float4 xq = *(const float4*)(s2 + a0);
#pragma unroll 4
            for (int g = gs; g < ge; g++) {
                int gn = (g + 1 < ge) ? (g + 1) : g;
                int an = offq(gn);
                float4 na = *(const float4*)(s0 + an);
                float4 np = *(const float4*)(s1 + an);
                float4 nq = *(const float4*)(s2 + an);
                stepw(v0, d0, xa.x); stepw(v1, d1, xp.x); stepw(v2, d2, xq.x);
                stepw(v0, d0, xa.y); stepw(v1, d1, xp.y); stepw(v2, d2, xq.y);
                stepw(v0, d0, xa.z); stepw(v1, d1, xp.z); stepw(v2, d2, xq.z);
                stepw(v0, d0, xa.w); stepw(v1, d1, xp.w); stepw(v2, d2, xq.w);
                xa = na; xp = np; xq = nq;
            }
        }
    }
    __syncthreads();   // all cross-thread warm-up reads done before s0 rewrite

    // ---- main scan: raw sal overwrites own s0 region in place ----
    float lmax = 0.f;
    unsigned long long loc[5] = {0ull, 0ull, 0ull, 0ull, 0ull};

    if (t < NSC) {
        int base = t * REG;
#pragma unroll 8
        for (int u = 0; u < CHUNK / 4; u++) {
            int a = base + (u << 2);
            float4 xa = *(const float4*)(s0 + a);
            float4 xp = *(const float4*)(s1 + a);
            float4 xq = *(const float4*)(s2 + a);
            float4 s4;
            s4.x = stepm(v0,d0,xa.x,w0) + stepm(v1,d1,xp.x,w1) + stepm(v2,d2,xq.x,w2);
            s4.y = stepm(v0,d0,xa.y,w0) + stepm(v1,d1,xp.y,w1) + stepm(v2,d2,xq.y,w2);
            s4.z = stepm(v0,d0,xa.z,w0) + stepm(v1,d1,xp.z,w1) + stepm(v2,d2,xq.z,w2);
            s4.w = stepm(v0,d0,xa.w,w0) + stepm(v1,d1,xp.w,w1) + stepm(v2,d2,xq.w,w2);
            lmax = fmaxf(lmax, fmaxf(fmaxf(s4.x, s4.y), fmaxf(s4.z, s4.w)));
            int e = start + (u << 2);
            ins5(loc, s4.x, e + 0);
            ins5(loc, s4.y, e + 1);
            ins5(loc, s4.z, e + 2);
            ins5(loc, s4.w, e + 3);
            *(float4*)(s0 + a) = s4;
        }
    }

    // ---- row max over 64 scan threads ----
    if (t < NSC) redf[t] = lmax;
    __syncthreads();
#pragma unroll
    for (int s = NSC / 2; s > 0; s >>= 1) {
        if (t < s) redf[t] = fmaxf(redf[t], redf[t + s]);
        __syncthreads();
    }
    float inv = 1.0f / (redf[0] + 1e-6f);

    // ---- normalize + coalesced store ----
    {
        float4* dst = (float4*)(salg + (size_t)b * T_DIM);
#pragma unroll
        for (int r = 0; r < T_DIM / 4 / NTH; r++) {
            int g = t + r * NTH;
            float4 v = *(const float4*)(s0 + offq(g));
            dst[g] = make_float4(v.x * inv, v.y * inv, v.z * inv, v.w * inv);
        }
    }

    // ---- top-5 block reduction (keys unique, stable order) ----
    float sum5 = 0.f;
    int p = 0;
    unsigned long long head = (t < NSC) ? loc[0] : 0ull;
    for (int r = 0; r < 5; r++) {
        if (t < NSC) redu[t] = head;
        __syncthreads();
#pragma unroll
        for (int s = NSC / 2; s > 0; s >>= 1) {
            if (t < s) {
                unsigned long long o = redu[t + s];
                if (o > redu[t]) redu[t] = o;
            }
            __syncthreads();
        }
        unsigned long long win = redu[0];
        __syncthreads();                 // before redu is rewritten next round

        if (t < NSC && head == win) {    // exactly one winner holds it
            p++;
            head = (p == 1) ? loc[1] :
                   (p == 2) ? loc[2] :
                   (p == 3) ? loc[3] :
                   (p == 4) ? loc[4] : 0ull;
        }
        if (t == 0) {
            float    val  = __uint_as_float((unsigned)(win >> 32));
            unsigned tidx = ~((unsigned)(win & 0xFFFFFFFFull));
            idx_out[b * 5 + r] = (float)tidx;
            sum5 += val * inv;
        }
        __syncthreads();
    }

    if (t == 0) {
        float avg = sum5 * 0.2f;
        mu[b] = 0.5f + 2.0f * tanhf(1.8f * avg);
    }
}

extern "C" void kernel_launch(void* const* d_in, const int* in_sizes, int n_in,
                              void* d_out, int out_size) {
    const float* amp      = (const float*)d_in[0];
    const float* pitch    = (const float*)d_in[1];
    const float* boundary = (const float*)d_in[2];
    const float* decay    = (const float*)d_in[3];
    const float* weights  = (const float*)d_in[4];

    float* out = (float*)d_out;
    float* mu  = out;                                    // [512]
    float* sal = out + B_DIM;                            // [512*8192]
    float* idx = out + B_DIM + (size_t)B_DIM * T_DIM;    // [512*5]

    cudaFuncSetAttribute(fused_kernel,
                         cudaFuncAttributeMaxDynamicSharedMemorySize, SMEM_BYTES);
    fused_kernel<<<B_DIM, NTH, SMEM_BYTES>>>(amp, pitch, boundary,
                                             decay, weights, mu, sal, idx);
}